// round 4
// baseline (speedup 1.0000x reference)
#include <cuda_runtime.h>
#include <cuda.h>
#include <cuda_bf16.h>
#include <cstdint>

// ============================================================
// Problem constants
// ============================================================
constexpr int N_ROWS = 4096;
constexpr int D_DIM  = 768;
constexpr float INV_T = 20.0f;   // 1 / 0.05

constexpr int BM = 128;          // anchor rows per CTA tile
constexpr int BN = 128;          // positive rows per CTA tile
constexpr int BK = 64;           // K chunk (64 bf16 = 128B row)
constexpr int MT = N_ROWS / BM;  // 32
constexpr int NT = N_ROWS / BN;  // 32
constexpr int NKC = D_DIM / BK;  // 12
constexpr int N_TILES = MT * NT; // 1024
constexpr int THREADS = 256;     // 8 warps: 2 (M) x 4 (N)
constexpr int STAGES = 3;
constexpr int GRID = 296;        // 2 x 148 SMs, persistent

constexpr int A_BYTES = BM * 128;              // 16384
constexpr int B_BYTES = BN * 128;              // 16384
constexpr int STAGE_BYTES = A_BYTES + B_BYTES; // 32768
// smem: [0,128) barriers, [128,640) rowsum, tiles from 1024
constexpr int SMEM_TOTAL = 1024 + STAGES * STAGE_BYTES;  // 99328

// ============================================================
// Device scratch (static — no allocation)
// ============================================================
__device__ __nv_bfloat16 g_A[N_ROWS * D_DIM];
__device__ __nv_bfloat16 g_B[N_ROWS * D_DIM];
__device__ float g_partials[NT * N_ROWS];
__device__ float g_last[N_ROWS];

// ============================================================
// Helpers
// ============================================================
__device__ __forceinline__ uint32_t smem_to_u32(const void* smem_ptr) {
    uint32_t addr;
    asm("{ .reg .u64 tmp; cvta.to.shared.u64 tmp, %1; cvt.u32.u64 %0, tmp; }"
        : "=r"(addr) : "l"(smem_ptr));
    return addr;
}

__device__ __forceinline__ uint32_t sw128(uint32_t off) {
    return off ^ ((off >> 3) & 0x70);
}

__device__ __forceinline__ void ldmatrix_x4(uint32_t* r, uint32_t addr) {
    asm volatile("ldmatrix.sync.aligned.m8n8.x4.shared.b16 {%0,%1,%2,%3}, [%4];"
                 : "=r"(r[0]), "=r"(r[1]), "=r"(r[2]), "=r"(r[3]) : "r"(addr));
}

__device__ __forceinline__ void mma16816(float* c, const uint32_t* a,
                                         const uint32_t* b) {
    asm volatile(
        "mma.sync.aligned.m16n8k16.row.col.f32.bf16.bf16.f32 "
        "{%0,%1,%2,%3}, {%4,%5,%6,%7}, {%8,%9}, {%0,%1,%2,%3};"
        : "+f"(c[0]), "+f"(c[1]), "+f"(c[2]), "+f"(c[3])
        : "r"(a[0]), "r"(a[1]), "r"(a[2]), "r"(a[3]), "r"(b[0]), "r"(b[1]));
}

#define MBARRIER_INIT(mbar, count) \
    asm volatile("mbarrier.init.shared.b64 [%0], %1;" \
                 :: "r"((uint32_t)(mbar)), "r"((uint32_t)(count)) : "memory")

#define MBARRIER_EXPECT_TX(mbar, bytes) \
    asm volatile("mbarrier.arrive.expect_tx.shared.b64 _, [%0], %1;" \
                 :: "r"((uint32_t)(mbar)), "r"((uint32_t)(bytes)) : "memory")

#define MBARRIER_ARRIVE(mbar) \
    asm volatile("mbarrier.arrive.shared.b64 _, [%0];" \
                 :: "r"((uint32_t)(mbar)) : "memory")

#define MBARRIER_WAIT_PARITY(mbar, parity) do { \
    uint32_t _mbar = (uint32_t)(mbar); \
    uint32_t _parity = (uint32_t)(parity); \
    uint32_t _done; \
    asm volatile( \
        "{\n\t" \
        ".reg .pred p;\n\t" \
        "mbarrier.try_wait.parity.acquire.cta.shared::cta.b64 p, [%1], %2;\n\t" \
        "selp.b32 %0, 1, 0, p;\n\t" \
        "}" \
        : "=r"(_done) : "r"(_mbar), "r"(_parity) : "memory"); \
    if (!_done) { \
        asm volatile( \
            "{\n\t" \
            ".reg .pred P1;\n\t" \
            "WAIT_LOOP_%=:\n\t" \
            "mbarrier.try_wait.parity.acquire.cta.shared::cta.b64 P1, [%0], %1, 0x989680;\n\t" \
            "@P1 bra.uni WAIT_DONE_%=;\n\t" \
            "bra.uni WAIT_LOOP_%=;\n\t" \
            "WAIT_DONE_%=:\n\t" \
            "}" \
            :: "r"(_mbar), "r"(_parity) : "memory"); \
    } \
} while(0)

#define TMA_LOAD_2D(smem_addr, tmap_ptr, cx, cy, mbar) \
    asm volatile( \
        "cp.async.bulk.tensor.2d.shared::cta.global.tile.mbarrier::complete_tx::bytes " \
        "[%0], [%1, {%2, %3}], [%4];" \
        :: "r"((uint32_t)(smem_addr)), "l"(tmap_ptr), \
           "r"((int)(cx)), "r"((int)(cy)), "r"((uint32_t)(mbar)) \
        : "memory")

// ============================================================
// Kernel 1: f32 -> bf16 conversion (8 independent loads/thread)
// ============================================================
__global__ void convert_kernel(const float* __restrict__ anchors,
                               const float* __restrict__ positives) {
    constexpr int Q4 = N_ROWS * D_DIM / 16;  // float4 count per quarter
    int i = blockIdx.x * blockDim.x + threadIdx.x;
    float4 a[4], p[4];
    #pragma unroll
    for (int h = 0; h < 4; ++h) {
        a[h] = reinterpret_cast<const float4*>(anchors)[i + h * Q4];
        p[h] = reinterpret_cast<const float4*>(positives)[i + h * Q4];
    }
    #pragma unroll
    for (int h = 0; h < 4; ++h) {
        int idx = i + h * Q4;
        reinterpret_cast<__nv_bfloat162*>(g_A)[2 * idx + 0] =
            __floats2bfloat162_rn(a[h].x, a[h].y);
        reinterpret_cast<__nv_bfloat162*>(g_A)[2 * idx + 1] =
            __floats2bfloat162_rn(a[h].z, a[h].w);
        reinterpret_cast<__nv_bfloat162*>(g_B)[2 * idx + 0] =
            __floats2bfloat162_rn(p[h].x, p[h].y);
        reinterpret_cast<__nv_bfloat162*>(g_B)[2 * idx + 1] =
            __floats2bfloat162_rn(p[h].z, p[h].w);
    }
}

// ============================================================
// Kernel 2: persistent TMA-fed bf16 HMMA GEMM + fused exp-rowsum
// 296 CTAs x (2 per SM). Tile t: mt = t & 31, nt = t >> 5.
// Continuous chunk pipeline across tiles (no per-tile drain).
// ============================================================
__global__ void __launch_bounds__(THREADS, 2)
gemm_epilogue_kernel(const __grid_constant__ CUtensorMap tmA,
                     const __grid_constant__ CUtensorMap tmB) {
    extern __shared__ char smem[];
    const int tid = threadIdx.x;
    const int lane = tid & 31;
    const int wid = tid >> 5;
    const int warpM = wid >> 2;  // 0..1 -> 64-row band
    const int warpN = wid & 3;   // 0..3 -> 32-col band
    const int bid = blockIdx.x;
    const uint32_t sb = smem_to_u32(smem);

    auto full_bar  = [&](int s) { return sb + s * 8; };
    auto empty_bar = [&](int s) { return sb + 64 + s * 8; };
    auto stage_off = [&](int s) { return sb + 1024 + (uint32_t)s * STAGE_BYTES; };

    // Number of tiles this CTA owns; total chunk sequence length
    const int n_local = (N_TILES - bid + GRID - 1) / GRID;
    const int total_chunks = n_local * NKC;

    if (tid == 0) {
        #pragma unroll
        for (int s = 0; s < STAGES; ++s) {
            MBARRIER_INIT(full_bar(s), 1);
            MBARRIER_INIT(empty_bar(s), THREADS);
        }
        asm volatile("fence.proxy.async.shared::cta;" ::: "memory");
    }
    __syncthreads();

    // Prologue: fill pipeline with first STAGES chunks of the sequence
    if (tid == 0) {
        #pragma unroll
        for (int q = 0; q < STAGES; ++q) {
            if (q < total_chunks) {
                int t = bid + (q / NKC) * GRID;
                int mt = t & (MT - 1), ntt = t >> 5, ck = q % NKC;
                MBARRIER_EXPECT_TX(full_bar(q), STAGE_BYTES);
                TMA_LOAD_2D(stage_off(q),           &tmA, ck * BK, mt * BM,
                            full_bar(q));
                TMA_LOAD_2D(stage_off(q) + A_BYTES, &tmB, ck * BK, ntt * BN,
                            full_bar(q));
            }
        }
    }

    // Fragment offsets (stage-relative)
    const uint32_t a_row = (uint32_t)(warpM * 64 + (lane & 15));
    const uint32_t a_kb  = (uint32_t)((lane >> 4) * 16);
    const uint32_t b_row = (uint32_t)(warpN * 32 + ((lane & 7) | ((lane >> 4) << 3)));
    const uint32_t b_kb  = (uint32_t)(((lane >> 3) & 1) * 16);

    float* rowsum = reinterpret_cast<float*>(smem + 128);

    int p = 0;  // global chunk sequence position
    for (int tl = 0; tl < n_local; ++tl) {
        const int tile = bid + tl * GRID;
        const int mt = tile & (MT - 1);
        const int nt = tile >> 5;

        float acc[16][4];  // [mi*4+ni][4]
        #pragma unroll
        for (int i = 0; i < 16; ++i)
            #pragma unroll
            for (int j = 0; j < 4; ++j) acc[i][j] = 0.0f;

        for (int c = 0; c < NKC; ++c, ++p) {
            const int s = p % STAGES;
            const int ph = (p / STAGES) & 1;
            MBARRIER_WAIT_PARITY(full_bar(s), ph);

            const uint32_t sA = stage_off(s);
            const uint32_t sB = sA + A_BYTES;

            #pragma unroll
            for (int ks = 0; ks < 4; ++ks) {
                uint32_t a[4][4];
                #pragma unroll
                for (int mi = 0; mi < 4; ++mi) {
                    uint32_t off = (a_row + mi * 16) * 128 + ks * 32 + a_kb;
                    ldmatrix_x4(a[mi], sA + sw128(off));
                }
                uint32_t b[2][4];
                #pragma unroll
                for (int np = 0; np < 2; ++np) {
                    uint32_t off = (b_row + np * 16) * 128 + ks * 32 + b_kb;
                    ldmatrix_x4(b[np], sB + sw128(off));
                }
                #pragma unroll
                for (int mi = 0; mi < 4; ++mi)
                    #pragma unroll
                    for (int ni = 0; ni < 4; ++ni)
                        mma16816(acc[mi * 4 + ni], a[mi],
                                 &b[ni >> 1][(ni & 1) * 2]);
            }

            MBARRIER_ARRIVE(empty_bar(s));

            // Producer: prefetch chunk p+STAGES (may belong to next tile)
            if (tid == 0) {
                const int q = p + STAGES;
                if (q < total_chunks) {
                    MBARRIER_WAIT_PARITY(empty_bar(s), ph);
                    const int t2 = bid + (q / NKC) * GRID;
                    const int mt2 = t2 & (MT - 1), nt2 = t2 >> 5;
                    const int ck2 = q % NKC;
                    MBARRIER_EXPECT_TX(full_bar(s), STAGE_BYTES);
                    TMA_LOAD_2D(stage_off(s),           &tmA, ck2 * BK,
                                mt2 * BM, full_bar(s));
                    TMA_LOAD_2D(stage_off(s) + A_BYTES, &tmB, ck2 * BK,
                                nt2 * BN, full_bar(s));
                }
            }
        }

        // ---- Fused epilogue (dedicated smem; safe vs. prefetch) ----
        __syncthreads();
        if (tid < BM) rowsum[tid] = 0.0f;
        __syncthreads();

        #pragma unroll
        for (int mi = 0; mi < 4; ++mi) {
            #pragma unroll
            for (int h = 0; h < 2; ++h) {
                const int lr = warpM * 64 + mi * 16 + h * 8 + (lane >> 2);
                const int grow = mt * BM + lr;
                float rs = 0.0f;
                #pragma unroll
                for (int ni = 0; ni < 4; ++ni) {
                    #pragma unroll
                    for (int j = 0; j < 2; ++j) {
                        float v = acc[mi * 4 + ni][h * 2 + j] * INV_T;
                        int gcol = nt * BN + warpN * 32 + ni * 8 +
                                   (lane & 3) * 2 + j;
                        float e = __expf(v);
                        rs += e;
                        if (gcol == grow) rs += e;       // diagonal double-count
                        if (gcol == N_ROWS - 1) g_last[grow] = v;
                    }
                }
                atomicAdd(&rowsum[lr], rs);
            }
        }
        __syncthreads();
        if (tid < BM)
            g_partials[nt * N_ROWS + mt * BM + tid] = rowsum[tid];
    }
}

// ============================================================
// Kernel 3: deterministic finalize (single block)
// ============================================================
__global__ void __launch_bounds__(1024)
finalize_kernel(float* __restrict__ out) {
    __shared__ float red[1024];
    const int t = threadIdx.x;
    float acc = 0.0f;
    for (int r = t; r < N_ROWS; r += 1024) {
        float denom = 0.0f;
        #pragma unroll
        for (int n = 0; n < NT; ++n)
            denom += g_partials[n * N_ROWS + r];
        acc += logf(denom) - g_last[r];  // loss_r = log(denom) - logits[r,-1]
    }
    red[t] = acc;
    __syncthreads();
    #pragma unroll
    for (int s = 512; s > 0; s >>= 1) {
        if (t < s) red[t] += red[t + s];
        __syncthreads();
    }
    if (t == 0) out[0] = red[0];
}

// ============================================================
// Launch
// ============================================================
typedef CUresult (*EncodeTiledFn)(
    CUtensorMap*, CUtensorMapDataType, cuuint32_t, void*,
    const cuuint64_t*, const cuuint64_t*, const cuuint32_t*, const cuuint32_t*,
    CUtensorMapInterleave, CUtensorMapSwizzle, CUtensorMapL2promotion,
    CUtensorMapFloatOOBfill);

extern "C" void kernel_launch(void* const* d_in, const int* in_sizes, int n_in,
                              void* d_out, int out_size) {
    const float* anchors   = (const float*)d_in[0];
    const float* positives = (const float*)d_in[1];
    float* out = (float*)d_out;

    void* fn = nullptr;
    cudaDriverEntryPointQueryResult qr;
    cudaGetDriverEntryPointByVersion("cuTensorMapEncodeTiled", &fn, 12000,
                                     cudaEnableDefault, &qr);
    EncodeTiledFn encode = (EncodeTiledFn)fn;

    void* pA = nullptr;
    void* pB = nullptr;
    cudaGetSymbolAddress(&pA, g_A);
    cudaGetSymbolAddress(&pB, g_B);

    CUtensorMap tmA, tmB;
    cuuint64_t dims[2]    = {(cuuint64_t)D_DIM, (cuuint64_t)N_ROWS};
    cuuint64_t strides[1] = {(cuuint64_t)D_DIM * sizeof(__nv_bfloat16)};
    cuuint32_t es[2]      = {1, 1};
    cuuint32_t box[2]     = {(cuuint32_t)BK, (cuuint32_t)BM};
    encode(&tmA, CU_TENSOR_MAP_DATA_TYPE_BFLOAT16, 2, pA, dims, strides, box,
           es, CU_TENSOR_MAP_INTERLEAVE_NONE, CU_TENSOR_MAP_SWIZZLE_128B,
           CU_TENSOR_MAP_L2_PROMOTION_L2_128B, CU_TENSOR_MAP_FLOAT_OOB_FILL_NONE);
    encode(&tmB, CU_TENSOR_MAP_DATA_TYPE_BFLOAT16, 2, pB, dims, strides, box,
           es, CU_TENSOR_MAP_INTERLEAVE_NONE, CU_TENSOR_MAP_SWIZZLE_128B,
           CU_TENSOR_MAP_L2_PROMOTION_L2_128B, CU_TENSOR_MAP_FLOAT_OOB_FILL_NONE);

    cudaFuncSetAttribute(gemm_epilogue_kernel,
                         cudaFuncAttributeMaxDynamicSharedMemorySize, SMEM_TOTAL);

    constexpr int Q4 = N_ROWS * D_DIM / 16;
    convert_kernel<<<Q4 / 256, 256>>>(anchors, positives);

    gemm_epilogue_kernel<<<GRID, THREADS, SMEM_TOTAL>>>(tmA, tmB);

    finalize_kernel<<<1, 1024>>>(out);
}